// round 7
// baseline (speedup 1.0000x reference)
#include <cuda_runtime.h>
#include <cstdint>

#define NB 8
#define NN 1024
#define NC 1024
#define NH 16
#define HD 64
#define TOPK 256

// ---------------- scratch (static device globals; no allocation) ----------------
__device__ float g_qkv[(size_t)NB * NN * 3 * NC];     // 8192 x 3072
__device__ float g_attn[(size_t)NB * NH * NN * NN];   // 128 x 1024 x 1024
__device__ float g_x[(size_t)NB * NN * NC];
__device__ float g_y[(size_t)NB * NN * NC];
__device__ float g_sim[NB * NN];
__device__ float g_pooled[NB * NC];
__device__ float g_visinv[NB];
__device__ unsigned char g_mask[NB * NN];             // canonical 0/1 mask

// ---------------- mask canonicalization (auto-detect uint8 vs int32 bool) ----------------
__global__ __launch_bounds__(256) void mask_canon_kernel(const unsigned char* __restrict__ raw) {
    __shared__ int red[256];
    int tid = threadIdx.x;
    int any = 0;
    for (int i = tid; i < NB * NN; i += 256)
        if ((i & 3) != 0 && raw[i] != 0) any = 1;
    red[tid] = any;
    __syncthreads();
#pragma unroll
    for (int off = 128; off > 0; off >>= 1) {
        if (tid < off) red[tid] |= red[tid + off];
        __syncthreads();
    }
    int is_u8 = red[0];
    const int* raw32 = (const int*)raw;
    for (int i = tid; i < NB * NN; i += 256) {
        unsigned char v = is_u8 ? (raw[i] != 0) : (raw32[i] != 0);
        g_mask[i] = v;
    }
}

// ---------------- helpers ----------------
__device__ __forceinline__ unsigned fkey(float f) {
    unsigned u = __float_as_uint(f);
    return (u & 0x80000000u) ? ~u : (u | 0x80000000u);
}

// shfl-based block reductions (256 threads, 8 warps). red8: 8-float smem scratch.
__device__ __forceinline__ float bsum8(float v, float* red8, int lane, int wid) {
#pragma unroll
    for (int off = 16; off > 0; off >>= 1) v += __shfl_xor_sync(0xffffffffu, v, off);
    __syncthreads();                 // protect red8 from any previous use
    if (lane == 0) red8[wid] = v;
    __syncthreads();
    float t = red8[0];
#pragma unroll
    for (int w = 1; w < 8; w++) t += red8[w];
    return t;
}

__device__ __forceinline__ float bmax8(float v, float* red8, int lane, int wid) {
#pragma unroll
    for (int off = 16; off > 0; off >>= 1) v = fmaxf(v, __shfl_xor_sync(0xffffffffu, v, off));
    __syncthreads();
    if (lane == 0) red8[wid] = v;
    __syncthreads();
    float t = red8[0];
#pragma unroll
    for (int w = 1; w < 8; w++) t = fmaxf(t, red8[w]);
    return t;
}

// legacy tree reductions (used by small kernels)
__device__ __forceinline__ float blk_reduce_sum(float v, float* red) {
    int tid = threadIdx.x;
    red[tid] = v;
    __syncthreads();
#pragma unroll
    for (int off = 128; off > 0; off >>= 1) {
        if (tid < off) red[tid] += red[tid + off];
        __syncthreads();
    }
    float r = red[0];
    __syncthreads();
    return r;
}

// Exact descending radix select over 1024 smem keys (256 threads) — used by pool_kernel.
__device__ __forceinline__ void radix_select_1024(const unsigned* sk, unsigned kwant,
                                                  unsigned* hist, unsigned* ss,
                                                  unsigned* sel, int tid) {
    if (tid == 0) { sel[0] = 0u; sel[1] = kwant; }
    unsigned pmask = 0u;
    __syncthreads();
    for (int shift = 24; shift >= 0; shift -= 8) {
        hist[tid] = 0u;
        __syncthreads();
        unsigned prefix = sel[0];
#pragma unroll
        for (int i = 0; i < 4; i++) {
            unsigned k = sk[tid + i * 256];
            if ((k & pmask) == prefix) atomicAdd(&hist[(k >> shift) & 255], 1u);
        }
        __syncthreads();
        ss[tid] = hist[tid];
        __syncthreads();
#pragma unroll
        for (int off = 1; off < 256; off <<= 1) {
            unsigned v = (tid + off < 256) ? ss[tid + off] : 0u;
            __syncthreads();
            ss[tid] += v;
            __syncthreads();
        }
        unsigned rem = sel[1];
        unsigned h = hist[tid];
        unsigned above = (tid < 255) ? ss[tid + 1] : 0u;
        __syncthreads();
        if (above < rem && above + h >= rem) {
            sel[0] = prefix | ((unsigned)tid << shift);
            sel[1] = rem - above;
        }
        pmask |= (0xFFu << shift);
        __syncthreads();
    }
}

// ---------------- generic fp32 GEMM (double-buffered): C = A*B + bias (+res) ----------------
// BM=128 BN=128 BK=16, 256 threads, 8x8 per thread, smem ping-pong, 1 sync/iter.
__global__ __launch_bounds__(256) void gemm_kernel(const float* __restrict__ A,
                                                   const float* __restrict__ B,
                                                   const float* __restrict__ bias,
                                                   const float* __restrict__ res,
                                                   float* __restrict__ C,
                                                   int M, int N, int K) {
    __shared__ float As[2][16][132];  // [buf][k][m]
    __shared__ float Bs[2][16][132];  // [buf][k][n]
    int tid = threadIdx.x;
    int m0 = blockIdx.y * 128, n0 = blockIdx.x * 128;
    int ty = tid >> 4, tx = tid & 15;
    // load-index precompute (2 float4 for A, 2 for B per iteration)
    int am[2], ak[2], bk[2], bn[2];
#pragma unroll
    for (int i = 0; i < 2; i++) {
        int lin = tid + i * 256;
        am[i] = lin >> 2;  ak[i] = (lin & 3) << 2;
        bk[i] = lin >> 5;  bn[i] = (lin & 31) << 2;
    }
    float acc[8][8];
#pragma unroll
    for (int r = 0; r < 8; r++)
#pragma unroll
        for (int c = 0; c < 8; c++) acc[r][c] = 0.f;

    float4 ra[2], rb[2];
#pragma unroll
    for (int i = 0; i < 2; i++) {
        ra[i] = *(const float4*)(A + (size_t)(m0 + am[i]) * K + ak[i]);
        rb[i] = *(const float4*)(B + (size_t)bk[i] * N + n0 + bn[i]);
    }
#pragma unroll
    for (int i = 0; i < 2; i++) {
        As[0][ak[i] + 0][am[i]] = ra[i].x; As[0][ak[i] + 1][am[i]] = ra[i].y;
        As[0][ak[i] + 2][am[i]] = ra[i].z; As[0][ak[i] + 3][am[i]] = ra[i].w;
        *(float4*)(&Bs[0][bk[i]][bn[i]]) = rb[i];
    }
    __syncthreads();

    int nit = K / 16;
    for (int it = 0; it < nit; it++) {
        int cur = it & 1;
        if (it + 1 < nit) {
            int k0 = (it + 1) * 16;
#pragma unroll
            for (int i = 0; i < 2; i++) {
                ra[i] = *(const float4*)(A + (size_t)(m0 + am[i]) * K + k0 + ak[i]);
                rb[i] = *(const float4*)(B + (size_t)(k0 + bk[i]) * N + n0 + bn[i]);
            }
        }
#pragma unroll
        for (int k = 0; k < 16; k++) {
            float a[8], bb[8];
            *(float4*)&a[0] = *(float4*)&As[cur][k][ty * 8];
            *(float4*)&a[4] = *(float4*)&As[cur][k][ty * 8 + 4];
            *(float4*)&bb[0] = *(float4*)&Bs[cur][k][tx * 8];
            *(float4*)&bb[4] = *(float4*)&Bs[cur][k][tx * 8 + 4];
#pragma unroll
            for (int r = 0; r < 8; r++)
#pragma unroll
                for (int c = 0; c < 8; c++) acc[r][c] += a[r] * bb[c];
        }
        if (it + 1 < nit) {
            int nxt = cur ^ 1;
#pragma unroll
            for (int i = 0; i < 2; i++) {
                As[nxt][ak[i] + 0][am[i]] = ra[i].x; As[nxt][ak[i] + 1][am[i]] = ra[i].y;
                As[nxt][ak[i] + 2][am[i]] = ra[i].z; As[nxt][ak[i] + 3][am[i]] = ra[i].w;
                *(float4*)(&Bs[nxt][bk[i]][bn[i]]) = rb[i];
            }
        }
        __syncthreads();
    }
#pragma unroll
    for (int r = 0; r < 8; r++) {
        int m = m0 + ty * 8 + r;
#pragma unroll
        for (int c = 0; c < 8; c += 4) {
            int n = n0 + tx * 8 + c;
            float4 v;
            v.x = acc[r][c + 0] + bias[n + 0];
            v.y = acc[r][c + 1] + bias[n + 1];
            v.z = acc[r][c + 2] + bias[n + 2];
            v.w = acc[r][c + 3] + bias[n + 3];
            if (res) {
                float4 rr = *(const float4*)(res + (size_t)m * N + n);
                v.x += rr.x; v.y += rr.y; v.z += rr.z; v.w += rr.w;
            }
            *(float4*)(C + (size_t)m * N + n) = v;
        }
    }
}

// ---------------- attn scores: 128x128 tile per block, BK=32 (K=64: 2 iters) ----------------
__global__ __launch_bounds__(256) void attn_gemm_kernel(const float* __restrict__ qkv,
                                                        float* __restrict__ attn) {
    __shared__ float Qs[32][132];  // [d][q]
    __shared__ float Ks[32][132];  // [d][ktok]
    int tid = threadIdx.x;
    int q0 = blockIdx.x * 128, k0 = blockIdx.y * 128;
    int bh = blockIdx.z;
    int b = bh >> 4, h = bh & 15;
    size_t qbase = ((size_t)b * NN + q0) * 3072 + h * 64;
    size_t kbase = ((size_t)b * NN + k0) * 3072 + 1024 + h * 64;
    int ty = tid >> 4, tx = tid & 15;
    float acc[8][8];
#pragma unroll
    for (int r = 0; r < 8; r++)
#pragma unroll
        for (int c = 0; c < 8; c++) acc[r][c] = 0.f;

    for (int d0 = 0; d0 < 64; d0 += 32) {
#pragma unroll
        for (int i = 0; i < 4; i++) {   // 1024 float4 per tile / 256 threads
            int lin = tid + i * 256;
            int m = lin >> 3;
            int dq = (lin & 7) << 2;
            float4 qv = *(const float4*)(qkv + qbase + (size_t)m * 3072 + d0 + dq);
            Qs[dq + 0][m] = qv.x; Qs[dq + 1][m] = qv.y;
            Qs[dq + 2][m] = qv.z; Qs[dq + 3][m] = qv.w;
            float4 kv = *(const float4*)(qkv + kbase + (size_t)m * 3072 + d0 + dq);
            Ks[dq + 0][m] = kv.x; Ks[dq + 1][m] = kv.y;
            Ks[dq + 2][m] = kv.z; Ks[dq + 3][m] = kv.w;
        }
        __syncthreads();
#pragma unroll
        for (int d = 0; d < 32; d++) {
            float a[8], bb[8];
            *(float4*)&a[0] = *(float4*)&Qs[d][ty * 8];
            *(float4*)&a[4] = *(float4*)&Qs[d][ty * 8 + 4];
            *(float4*)&bb[0] = *(float4*)&Ks[d][tx * 8];
            *(float4*)&bb[4] = *(float4*)&Ks[d][tx * 8 + 4];
#pragma unroll
            for (int r = 0; r < 8; r++)
#pragma unroll
                for (int c = 0; c < 8; c++) acc[r][c] += a[r] * bb[c];
        }
        __syncthreads();
    }
    const float scale = 0.125f;
#pragma unroll
    for (int r = 0; r < 8; r++) {
#pragma unroll
        for (int c = 0; c < 8; c += 4) {
            float4 v;
            v.x = acc[r][c + 0] * scale; v.y = acc[r][c + 1] * scale;
            v.z = acc[r][c + 2] * scale; v.w = acc[r][c + 3] * scale;
            *(float4*)(attn + ((size_t)bh * NN + q0 + ty * 8 + r) * NN + k0 + tx * 8 + c) = v;
        }
    }
}

// ---------------- per-row top-256 + double softmax (regs + shfl scans) ----------------
__global__ __launch_bounds__(256) void topk_softmax_kernel(float* __restrict__ attn) {
    int row = blockIdx.x;            // (b*16+h)*1024 + q
    int b = row >> 14;
    int tid = threadIdx.x;
    int lane = tid & 31, wid = tid >> 5;
    float* a = attn + (size_t)row * NN;
    __shared__ unsigned hist[256];
    __shared__ unsigned wtot[8];
    __shared__ float red8[8];
    __shared__ unsigned sel[3];
    __shared__ unsigned s_sk[1024];      // for rare tie path
    __shared__ unsigned char tieflag[1024];
    __shared__ int s_partial;

    float v[4];
    unsigned k[4];
    unsigned char mk[4];
    float lm = -3.4e38f;
#pragma unroll
    for (int i = 0; i < 4; i++) {
        int idx = tid + i * 256;
        v[i] = a[idx];
        k[i] = fkey(v[i]);
        s_sk[idx] = k[i];
        mk[i] = g_mask[b * NN + idx];
        lm = fmaxf(lm, v[i]);
    }
    if (tid == 0) { sel[0] = 0u; sel[1] = TOPK; }
    float m = bmax8(lm, red8, lane, wid);   // syncs make sel[] init visible too

    unsigned pmask = 0u;
#pragma unroll
    for (int shift = 24; shift >= 0; shift -= 8) {
        hist[tid] = 0u;
        unsigned prefix = sel[0];
        unsigned rem = sel[1];
        __syncthreads();
#pragma unroll
        for (int i = 0; i < 4; i++)
            if ((k[i] & pmask) == prefix) atomicAdd(&hist[(k[i] >> shift) & 255], 1u);
        __syncthreads();
        unsigned h = hist[tid];
        unsigned s = h;
#pragma unroll
        for (int off = 1; off < 32; off <<= 1) {
            unsigned n = __shfl_down_sync(0xffffffffu, s, off);
            if (lane + off < 32) s += n;
        }
        unsigned wt = __shfl_sync(0xffffffffu, s, 0);
        if (lane == 0) wtot[wid] = wt;
        __syncthreads();
        unsigned woff = 0;
        for (int w = wid + 1; w < 8; w++) woff += wtot[w];
        unsigned incl = s + woff;       // count of keys in bins >= tid
        unsigned above = incl - h;      // strictly greater bins
        if (above < rem && incl >= rem) {
            sel[0] = prefix | ((unsigned)tid << shift);
            sel[1] = rem - above;
            sel[2] = h;                 // at shift==0 this is exact cnt_eq
        }
        pmask |= (0xFFu << shift);
        __syncthreads();
    }
    unsigned tk = sel[0], rem = sel[1], cnt_eq = sel[2];

    if (tid == 0) {
        s_partial = (rem < cnt_eq);
        if (rem < cnt_eq) {             // rare: partial ties, lowest indices win
            unsigned taken = 0;
            for (int kk = 0; kk < 1024; kk++) {
                unsigned char f = (s_sk[kk] == tk && taken < rem) ? 1 : 0;
                tieflag[kk] = f;
                taken += f;
            }
        }
    }
    __syncthreads();
    int partial = s_partial;

    bool inc[4];
#pragma unroll
    for (int i = 0; i < 4; i++)
        inc[i] = (k[i] > tk) || (k[i] == tk && (!partial || tieflag[tid + i * 256]));

    float lS = 0.f;
#pragma unroll
    for (int i = 0; i < 4; i++)
        if (inc[i]) lS += __expf(v[i] - m);
    float S = bsum8(lS, red8, lane, wid);
    float invS = 1.f / S;

    float lz = 0.f, e[4];
#pragma unroll
    for (int i = 0; i < 4; i++) {
        e[i] = mk[i] ? 0.f : (inc[i] ? __expf(__expf(v[i] - m) * invS) : 1.f);
        lz += e[i];
    }
    float Z = bsum8(lz, red8, lane, wid);
    float invZ = 1.f / Z;
#pragma unroll
    for (int i = 0; i < 4; i++)
        a[tid + i * 256] = e[i] * invZ;
}

// ---------------- AV: two heads per block -> 128(q) x 128(2*hd) tile, BK=16 ----------------
__global__ __launch_bounds__(256) void av_gemm_kernel(const float* __restrict__ attn,
                                                      const float* __restrict__ qkv,
                                                      float* __restrict__ x) {
    __shared__ float Ws0[16][132];  // [k][q] head hp*2
    __shared__ float Ws1[16][132];  // [k][q] head hp*2+1
    __shared__ float Vs[16][132];   // [k][d 0..127 = two heads]
    int tid = threadIdx.x;
    int q0 = blockIdx.x * 128;
    int bhp = blockIdx.y;            // b*8 + hp
    int b = bhp >> 3, hp = bhp & 7;
    int bh0 = b * 16 + hp * 2;
    int ty = tid >> 4, tx = tid & 15;
    // load-index precompute
    int wq[2], wk, vk[2], vd;
    wq[0] = tid >> 2; wq[1] = (tid >> 2) + 64; wk = (tid & 3) << 2;
    vk[0] = tid >> 5; vk[1] = (tid >> 5) + 8;  vd = (tid & 31) << 2;
    const float* w0base = attn + (size_t)bh0 * NN * NN;
    const float* w1base = attn + (size_t)(bh0 + 1) * NN * NN;
    const float* vbase = qkv + (size_t)b * NN * 3072 + 2048 + hp * 128;

    float acc[8][8];
#pragma unroll
    for (int r = 0; r < 8; r++)
#pragma unroll
        for (int c = 0; c < 8; c++) acc[r][c] = 0.f;

    float4 rw0[2], rw1[2], rv[2];
    // prologue: load kt=0
#pragma unroll
    for (int i = 0; i < 2; i++) {
        rw0[i] = *(const float4*)(w0base + (size_t)(q0 + wq[i]) * NN + wk);
        rw1[i] = *(const float4*)(w1base + (size_t)(q0 + wq[i]) * NN + wk);
        rv[i]  = *(const float4*)(vbase + (size_t)vk[i] * 3072 + vd);
    }
    float (*Wsel)[132] = (tx < 8) ? Ws0 : Ws1;
    int txc = (tx < 8) ? tx * 8 : (tx - 8) * 8 + 64;  // column base in Vs for this thread
    (void)txc;

    const int NIT = NN / 16;
    for (int it = 0; it < NIT; it++) {
#pragma unroll
        for (int i = 0; i < 2; i++) {
            Ws0[wk + 0][wq[i]] = rw0[i].x; Ws0[wk + 1][wq[i]] = rw0[i].y;
            Ws0[wk + 2][wq[i]] = rw0[i].z; Ws0[wk + 3][wq[i]] = rw0[i].w;
            Ws1[wk + 0][wq[i]] = rw1[i].x; Ws1[wk + 1][wq[i]] = rw1[i].y;
            Ws1[wk + 2][wq[i]] = rw1[i].z; Ws1[wk + 3][wq[i]] = rw1[i].w;
            *(float4*)(&Vs[vk[i]][vd]) = rv[i];
        }
        __syncthreads();
        if (it + 1 < NIT) {
            int kt = (it + 1) * 16;
#pragma unroll
            for (int i = 0; i < 2; i++) {
                rw0[i] = *(const float4*)(w0base + (size_t)(q0 + wq[i]) * NN + kt + wk);
                rw1[i] = *(const float4*)(w1base + (size_t)(q0 + wq[i]) * NN + kt + wk);
                rv[i]  = *(const float4*)(vbase + (size_t)(kt + vk[i]) * 3072 + vd);
            }
        }
#pragma unroll
        for (int kk = 0; kk < 16; kk++) {
            float a[8], bb[8];
            *(float4*)&a[0] = *(float4*)&Wsel[kk][ty * 8];
            *(float4*)&a[4] = *(float4*)&Wsel[kk][ty * 8 + 4];
            *(float4*)&bb[0] = *(float4*)&Vs[kk][tx * 8];
            *(float4*)&bb[4] = *(float4*)&Vs[kk][tx * 8 + 4];
#pragma unroll
            for (int r = 0; r < 8; r++)
#pragma unroll
                for (int c = 0; c < 8; c++) acc[r][c] += a[r] * bb[c];
        }
        __syncthreads();
    }
#pragma unroll
    for (int r = 0; r < 8; r++) {
#pragma unroll
        for (int c = 0; c < 8; c += 4) {
            float4 v;
            v.x = acc[r][c + 0]; v.y = acc[r][c + 1];
            v.z = acc[r][c + 2]; v.w = acc[r][c + 3];
            *(float4*)(x + ((size_t)b * NN + q0 + ty * 8 + r) * NC + hp * 128 + tx * 8 + c) = v;
        }
    }
}

// ---------------- row layernorm over 1024 ----------------
__global__ __launch_bounds__(256) void ln_kernel(const float* __restrict__ in,
                                                 const float* __restrict__ g,
                                                 const float* __restrict__ bt,
                                                 float* __restrict__ out) {
    int row = blockIdx.x, tid = threadIdx.x;
    int lane = tid & 31, wid = tid >> 5;
    __shared__ float red8[8];
    const float* p = in + (size_t)row * 1024;
    float xv[4];
    float s = 0.f;
#pragma unroll
    for (int i = 0; i < 4; i++) {
        xv[i] = p[tid + i * 256];
        s += xv[i];
    }
    float mu = bsum8(s, red8, lane, wid) * (1.f / 1024.f);
    float vs = 0.f;
#pragma unroll
    for (int i = 0; i < 4; i++) {
        float d = xv[i] - mu;
        vs += d * d;
    }
    float var = bsum8(vs, red8, lane, wid) * (1.f / 1024.f);
    float rstd = rsqrtf(var + 1e-5f);
#pragma unroll
    for (int i = 0; i < 4; i++) {
        int idx = tid + i * 256;
        out[(size_t)row * 1024 + idx] = (xv[i] - mu) * rstd * g[idx] + bt[idx];
    }
}

// ---------------- vis token inverse norms ----------------
__global__ __launch_bounds__(256) void visnorm_kernel(const float* __restrict__ vis,
                                                      float* __restrict__ visinv) {
    int b = blockIdx.x, tid = threadIdx.x;
    int lane = tid & 31, wid = tid >> 5;
    __shared__ float red8[8];
    float s = 0.f;
#pragma unroll
    for (int i = 0; i < 4; i++) {
        float v = vis[b * 1024 + tid + i * 256];
        s += v * v;
    }
    float t = bsum8(s, red8, lane, wid);
    if (tid == 0) visinv[b] = 1.f / fmaxf(sqrtf(t), 1e-12f);
}

// ---------------- sim = sigmoid(beta + alpha * dot(vis_n, tf_n)), masked -> 0 ----------------
__global__ __launch_bounds__(256) void sim_kernel(const float* __restrict__ vis,
                                                  const float* __restrict__ tf,
                                                  const float* __restrict__ alpha,
                                                  const float* __restrict__ beta,
                                                  const float* __restrict__ visinv,
                                                  float* __restrict__ sim) {
    int bn = blockIdx.x;  // b*1024 + n
    int b = bn >> 10;
    int tid = threadIdx.x;
    int lane = tid & 31, wid = tid >> 5;
    __shared__ float red8[8];
    const float* vrow = vis + b * 1024;
    const float* trow = tf + (size_t)bn * 1024;
    float tv[4], vv[4];
    float q = 0.f;
#pragma unroll
    for (int i = 0; i < 4; i++) {
        int idx = tid + i * 256;
        tv[i] = trow[idx];
        vv[i] = vrow[idx];
        q += tv[i] * tv[i];
    }
    q = bsum8(q, red8, lane, wid);
    float invt = 1.f / fmaxf(sqrtf(q), 1e-12f);
    float vi = visinv[b];
    float d = 0.f;
#pragma unroll
    for (int i = 0; i < 4; i++)
        d += (vv[i] * vi) * (tv[i] * invt);
    d = bsum8(d, red8, lane, wid);
    if (tid == 0) {
        float s;
        if (g_mask[bn]) {
            s = 0.f;  // sigmoid(-inf)
        } else {
            float val = beta[0] + alpha[0] * d;
            s = 1.f / (1.f + __expf(-val));
        }
        sim[bn] = s;
    }
}

// ---------------- top-256 sim pooling + txt_token add ----------------
__global__ __launch_bounds__(256) void pool_kernel(const float* __restrict__ sim,
                                                   const float* __restrict__ tf,
                                                   const float* __restrict__ txt,
                                                   float* __restrict__ pooled) {
    int b = blockIdx.x, tid = threadIdx.x;
    __shared__ unsigned sk[1024];
    __shared__ unsigned hist[256];
    __shared__ unsigned ss[256];
    __shared__ unsigned sel[2];
    __shared__ unsigned char tieflag[1024];
    __shared__ int s_partial;
    __shared__ unsigned sc[256];
    __shared__ short list[256];
#pragma unroll
    for (int i = 0; i < 4; i++) {
        int idx = tid + i * 256;
        sk[idx] = fkey(sim[b * 1024 + idx]);
    }
    __syncthreads();
    radix_select_1024(sk, TOPK, hist, ss, sel, tid);
    unsigned tk = sel[0];
    unsigned rem = sel[1];
    if (tid == 0) hist[0] = 0;
    __syncthreads();
#pragma unroll
    for (int i = 0; i < 4; i++)
        if (sk[tid + i * 256] == tk) atomicAdd(&hist[0], 1u);
    __syncthreads();
    unsigned cnt_eq = hist[0];
    if (tid == 0) {
        s_partial = (rem < cnt_eq);
        if (rem < cnt_eq) {  // ties (masked entries are all exactly 0): lowest indices win
            unsigned taken = 0;
            for (int k = 0; k < 1024; k++) {
                unsigned char f = (sk[k] == tk && taken < rem) ? 1 : 0;
                tieflag[k] = f;
                taken += f;
            }
        }
    }
    __syncthreads();
    int partial = s_partial;

    int base = tid * 4;
    unsigned cnt = 0;
    unsigned char f[4];
#pragma unroll
    for (int j = 0; j < 4; j++) {
        int k = base + j;
        unsigned kk = sk[k];
        bool inc = (kk > tk) || (kk == tk && (!partial || tieflag[k]));
        f[j] = inc;
        cnt += inc;
    }
    sc[tid] = cnt;
    __syncthreads();
#pragma unroll
    for (int off = 1; off < 256; off <<= 1) {
        unsigned v = (tid >= off) ? sc[tid - off] : 0u;
        __syncthreads();
        sc[tid] += v;
        __syncthreads();
    }
    unsigned pos = sc[tid] - cnt;
#pragma unroll
    for (int j = 0; j < 4; j++)
        if (f[j]) list[pos++] = (short)(base + j);
    __syncthreads();

    float acc[4] = {0.f, 0.f, 0.f, 0.f};
    for (int j = 0; j < TOPK; j++) {
        int n = list[j];
        const float* rrow = tf + ((size_t)b * 1024 + n) * 1024;
#pragma unroll
        for (int i = 0; i < 4; i++) acc[i] += rrow[tid + i * 256];
    }
#pragma unroll
    for (int i = 0; i < 4; i++) {
        int c = tid + i * 256;
        pooled[b * 1024 + c] = acc[i] * (1.f / 256.f) + txt[b * 1024 + c];
    }
}

// ---------------- tt = LN(pooled @ Wp1 + bp1) ----------------
__global__ __launch_bounds__(256) void final_kernel(const float* __restrict__ pooled,
                                                    const float* __restrict__ W,
                                                    const float* __restrict__ bias,
                                                    const float* __restrict__ g,
                                                    const float* __restrict__ bt,
                                                    float* __restrict__ out) {
    int b = blockIdx.x, tid = threadIdx.x;
    int lane = tid & 31, wid = tid >> 5;
    __shared__ float ts[1024];
    __shared__ float red8[8];
#pragma unroll
    for (int i = 0; i < 4; i++) ts[tid + i * 256] = pooled[b * 1024 + tid + i * 256];
    __syncthreads();
    float acc[4] = {0.f, 0.f, 0.f, 0.f};
#pragma unroll 4
    for (int c = 0; c < 1024; c++) {
        float tc = ts[c];
        const float* wr = W + (size_t)c * 1024 + tid;
        acc[0] += tc * wr[0];
        acc[1] += tc * wr[256];
        acc[2] += tc * wr[512];
        acc[3] += tc * wr[768];
    }
    float ys[4];
    float s = 0.f;
#pragma unroll
    for (int i = 0; i < 4; i++) {
        ys[i] = acc[i] + bias[tid + i * 256];
        s += ys[i];
    }
    float mu = bsum8(s, red8, lane, wid) * (1.f / 1024.f);
    float vs = 0.f;
#pragma unroll
    for (int i = 0; i < 4; i++) {
        float d = ys[i] - mu;
        vs += d * d;
    }
    float var = bsum8(vs, red8, lane, wid) * (1.f / 1024.f);
    float rstd = rsqrtf(var + 1e-5f);
#pragma unroll
    for (int i = 0; i < 4; i++) {
        int idx = tid + i * 256;
        out[b * 1024 + idx] = (ys[i] - mu) * rstd * g[idx] + bt[idx];
    }
}

// ---------------- host launch ----------------
extern "C" void kernel_launch(void* const* d_in, const int* in_sizes, int n_in,
                              void* d_out, int out_size) {
    const float* txt_token = (const float*)d_in[0];
    const float* text_features = (const float*)d_in[1];
    const unsigned char* text_mask = (const unsigned char*)d_in[2];
    const float* vis_token = (const float*)d_in[3];
    int o = (n_in > 4 && in_sizes[4] == 1) ? 1 : 0;
    const float* Wqkv = (const float*)d_in[4 + o];
    const float* bqkv = (const float*)d_in[5 + o];
    const float* Wp2 = (const float*)d_in[6 + o];
    const float* bp2 = (const float*)d_in[7 + o];
    const float* ln2_g = (const float*)d_in[8 + o];
    const float* ln2_b = (const float*)d_in[9 + o];
    const float* sim_alpha = (const float*)d_in[10 + o];
    const float* sim_beta = (const float*)d_in[11 + o];
    const float* Wp1 = (const float*)d_in[12 + o];
    const float* bp1 = (const float*)d_in[13 + o];
    const float* ln1_g = (const float*)d_in[14 + o];
    const float* ln1_b = (const float*)d_in[15 + o];

    float* out = (float*)d_out;
    float* tt = out;                 // (8,1,1024)
    float* tf = out + NB * NC;       // (8,1024,1024)

    float *qkv, *attn, *x, *y, *simv, *pooled, *visinv;
    cudaGetSymbolAddress((void**)&qkv, g_qkv);
    cudaGetSymbolAddress((void**)&attn, g_attn);
    cudaGetSymbolAddress((void**)&x, g_x);
    cudaGetSymbolAddress((void**)&y, g_y);
    cudaGetSymbolAddress((void**)&simv, g_sim);
    cudaGetSymbolAddress((void**)&pooled, g_pooled);
    cudaGetSymbolAddress((void**)&visinv, g_visinv);

    // 0. canonicalize mask
    mask_canon_kernel<<<1, 256>>>(text_mask);
    // 1. qkv = X @ Wqkv + bqkv
    gemm_kernel<<<dim3(3072 / 128, 8192 / 128), 256>>>(text_features, Wqkv, bqkv, nullptr,
                                                       qkv, 8192, 3072, 1024);
    // 2. attn = Q K^T * scale   (128x128 tiles)
    attn_gemm_kernel<<<dim3(8, 8, 128), 256>>>(qkv, attn);
    // 3. top-256 + double softmax (in place)
    topk_softmax_kernel<<<NB * NH * NN, 256>>>(attn);
    // 4. x = attn_w @ V  (two heads per block)
    av_gemm_kernel<<<dim3(8, 64), 256>>>(attn, qkv, x);
    // 5. y = x @ Wp2 + bp2 + text_features
    gemm_kernel<<<dim3(1024 / 128, 8192 / 128), 256>>>(x, Wp2, bp2, text_features,
                                                       y, 8192, 1024, 1024);
    // 6. tf = layernorm(y)
    ln_kernel<<<8192, 256>>>(y, ln2_g, ln2_b, tf);
    // 7-8. sim
    visnorm_kernel<<<NB, 256>>>(vis_token, visinv);
    sim_kernel<<<NB * NN, 256>>>(vis_token, tf, sim_alpha, sim_beta, visinv, simv);
    // 9. pooled (+ txt_token)
    pool_kernel<<<NB, 256>>>(simv, tf, txt_token, pooled);
    // 10. tt = LN(pooled @ Wp1 + bp1)
    final_kernel<<<NB, 256>>>(pooled, Wp1, bp1, ln1_g, ln1_b, tt);
    (void)out_size;
}

// round 11
// speedup vs baseline: 1.6111x; 1.6111x over previous
#include <cuda_runtime.h>
#include <cstdint>

#define NB 8
#define NN 1024
#define NC 1024
#define NH 16
#define HD 64
#define TOPK 256

// ---------------- scratch (static device globals; no allocation) ----------------
__device__ float g_qkv[(size_t)NB * NN * 3 * NC];     // 8192 x 3072
__device__ float g_attn[(size_t)NB * NH * NN * NN];   // 128 x 1024 x 1024
__device__ float g_x[(size_t)NB * NN * NC];
__device__ float g_y[(size_t)NB * NN * NC];
__device__ float g_sim[NB * NN];
__device__ float g_pooled[NB * NC];
__device__ float g_visinv[NB];
__device__ unsigned char g_mask[NB * NN];             // canonical 0/1 mask

// ---------------- mask canonicalization (auto-detect uint8 vs int32 bool) ----------------
__global__ __launch_bounds__(256) void mask_canon_kernel(const unsigned char* __restrict__ raw) {
    __shared__ int red[256];
    int tid = threadIdx.x;
    int any = 0;
    for (int i = tid; i < NB * NN; i += 256)
        if ((i & 3) != 0 && raw[i] != 0) any = 1;
    red[tid] = any;
    __syncthreads();
#pragma unroll
    for (int off = 128; off > 0; off >>= 1) {
        if (tid < off) red[tid] |= red[tid + off];
        __syncthreads();
    }
    int is_u8 = red[0];
    const int* raw32 = (const int*)raw;
    for (int i = tid; i < NB * NN; i += 256) {
        unsigned char v = is_u8 ? (raw[i] != 0) : (raw32[i] != 0);
        g_mask[i] = v;
    }
}

// ---------------- helpers ----------------
__device__ __forceinline__ unsigned fkey(float f) {
    unsigned u = __float_as_uint(f);
    return (u & 0x80000000u) ? ~u : (u | 0x80000000u);
}

// shfl-based block reductions (256 threads, 8 warps). red8: 8-float smem scratch.
__device__ __forceinline__ float bsum8(float v, float* red8, int lane, int wid) {
#pragma unroll
    for (int off = 16; off > 0; off >>= 1) v += __shfl_xor_sync(0xffffffffu, v, off);
    __syncthreads();
    if (lane == 0) red8[wid] = v;
    __syncthreads();
    float t = red8[0];
#pragma unroll
    for (int w = 1; w < 8; w++) t += red8[w];
    return t;
}

__device__ __forceinline__ float bmax8(float v, float* red8, int lane, int wid) {
#pragma unroll
    for (int off = 16; off > 0; off >>= 1) v = fmaxf(v, __shfl_xor_sync(0xffffffffu, v, off));
    __syncthreads();
    if (lane == 0) red8[wid] = v;
    __syncthreads();
    float t = red8[0];
#pragma unroll
    for (int w = 1; w < 8; w++) t = fmaxf(t, red8[w]);
    return t;
}

// Exact descending radix select over 1024 smem keys (256 threads) — used by pool_kernel.
__device__ __forceinline__ void radix_select_1024(const unsigned* sk, unsigned kwant,
                                                  unsigned* hist, unsigned* ss,
                                                  unsigned* sel, int tid) {
    if (tid == 0) { sel[0] = 0u; sel[1] = kwant; }
    unsigned pmask = 0u;
    __syncthreads();
    for (int shift = 24; shift >= 0; shift -= 8) {
        hist[tid] = 0u;
        __syncthreads();
        unsigned prefix = sel[0];
#pragma unroll
        for (int i = 0; i < 4; i++) {
            unsigned k = sk[tid + i * 256];
            if ((k & pmask) == prefix) atomicAdd(&hist[(k >> shift) & 255], 1u);
        }
        __syncthreads();
        ss[tid] = hist[tid];
        __syncthreads();
#pragma unroll
        for (int off = 1; off < 256; off <<= 1) {
            unsigned v = (tid + off < 256) ? ss[tid + off] : 0u;
            __syncthreads();
            ss[tid] += v;
            __syncthreads();
        }
        unsigned rem = sel[1];
        unsigned h = hist[tid];
        unsigned above = (tid < 255) ? ss[tid + 1] : 0u;
        __syncthreads();
        if (above < rem && above + h >= rem) {
            sel[0] = prefix | ((unsigned)tid << shift);
            sel[1] = rem - above;
        }
        pmask |= (0xFFu << shift);
        __syncthreads();
    }
}

// ---------------- generic fp32 GEMM (R6 known-good single-buffer): C = A*B + bias (+res) ----------------
__global__ __launch_bounds__(256) void gemm_kernel(const float* __restrict__ A,
                                                   const float* __restrict__ B,
                                                   const float* __restrict__ bias,
                                                   const float* __restrict__ res,
                                                   float* __restrict__ C,
                                                   int M, int N, int K) {
    __shared__ float As[16][132];  // [k][m]
    __shared__ float Bs[16][132];  // [k][n]
    int tid = threadIdx.x;
    int m0 = blockIdx.y * 128, n0 = blockIdx.x * 128;
    int ty = tid >> 4, tx = tid & 15;
    float acc[8][8];
#pragma unroll
    for (int r = 0; r < 8; r++)
#pragma unroll
        for (int c = 0; c < 8; c++) acc[r][c] = 0.f;

    for (int k0 = 0; k0 < K; k0 += 16) {
#pragma unroll
        for (int i = 0; i < 2; i++) {
            int lin = tid + i * 256;
            int m = lin >> 2;
            int kq = (lin & 3) << 2;
            float4 v = *(const float4*)(A + (size_t)(m0 + m) * K + k0 + kq);
            As[kq + 0][m] = v.x; As[kq + 1][m] = v.y;
            As[kq + 2][m] = v.z; As[kq + 3][m] = v.w;
        }
#pragma unroll
        for (int i = 0; i < 2; i++) {
            int lin = tid + i * 256;
            int k = lin >> 5;
            int nq = (lin & 31) << 2;
            *(float4*)(&Bs[k][nq]) = *(const float4*)(B + (size_t)(k0 + k) * N + n0 + nq);
        }
        __syncthreads();
#pragma unroll
        for (int k = 0; k < 16; k++) {
            float a[8], bb[8];
            *(float4*)&a[0] = *(float4*)&As[k][ty * 8];
            *(float4*)&a[4] = *(float4*)&As[k][ty * 8 + 4];
            *(float4*)&bb[0] = *(float4*)&Bs[k][tx * 8];
            *(float4*)&bb[4] = *(float4*)&Bs[k][tx * 8 + 4];
#pragma unroll
            for (int r = 0; r < 8; r++)
#pragma unroll
                for (int c = 0; c < 8; c++) acc[r][c] += a[r] * bb[c];
        }
        __syncthreads();
    }
#pragma unroll
    for (int r = 0; r < 8; r++) {
        int m = m0 + ty * 8 + r;
#pragma unroll
        for (int c = 0; c < 8; c += 4) {
            int n = n0 + tx * 8 + c;
            float4 v;
            v.x = acc[r][c + 0] + bias[n + 0];
            v.y = acc[r][c + 1] + bias[n + 1];
            v.z = acc[r][c + 2] + bias[n + 2];
            v.w = acc[r][c + 3] + bias[n + 3];
            if (res) {
                float4 rr = *(const float4*)(res + (size_t)m * N + n);
                v.x += rr.x; v.y += rr.y; v.z += rr.z; v.w += rr.w;
            }
            *(float4*)(C + (size_t)m * N + n) = v;
        }
    }
}

// ---------------- attn scores: 128x128 tile per block, BK=32 (K=64: 2 iters) ----------------
__global__ __launch_bounds__(256) void attn_gemm_kernel(const float* __restrict__ qkv,
                                                        float* __restrict__ attn) {
    __shared__ float Qs[32][132];  // [d][q]
    __shared__ float Ks[32][132];  // [d][ktok]
    int tid = threadIdx.x;
    int q0 = blockIdx.x * 128, k0 = blockIdx.y * 128;
    int bh = blockIdx.z;
    int b = bh >> 4, h = bh & 15;
    size_t qbase = ((size_t)b * NN + q0) * 3072 + h * 64;
    size_t kbase = ((size_t)b * NN + k0) * 3072 + 1024 + h * 64;
    int ty = tid >> 4, tx = tid & 15;
    float acc[8][8];
#pragma unroll
    for (int r = 0; r < 8; r++)
#pragma unroll
        for (int c = 0; c < 8; c++) acc[r][c] = 0.f;

    for (int d0 = 0; d0 < 64; d0 += 32) {
#pragma unroll
        for (int i = 0; i < 4; i++) {
            int lin = tid + i * 256;
            int m = lin >> 3;
            int dq = (lin & 7) << 2;
            float4 qv = *(const float4*)(qkv + qbase + (size_t)m * 3072 + d0 + dq);
            Qs[dq + 0][m] = qv.x; Qs[dq + 1][m] = qv.y;
            Qs[dq + 2][m] = qv.z; Qs[dq + 3][m] = qv.w;
            float4 kv = *(const float4*)(qkv + kbase + (size_t)m * 3072 + d0 + dq);
            Ks[dq + 0][m] = kv.x; Ks[dq + 1][m] = kv.y;
            Ks[dq + 2][m] = kv.z; Ks[dq + 3][m] = kv.w;
        }
        __syncthreads();
#pragma unroll
        for (int d = 0; d < 32; d++) {
            float a[8], bb[8];
            *(float4*)&a[0] = *(float4*)&Qs[d][ty * 8];
            *(float4*)&a[4] = *(float4*)&Qs[d][ty * 8 + 4];
            *(float4*)&bb[0] = *(float4*)&Ks[d][tx * 8];
            *(float4*)&bb[4] = *(float4*)&Ks[d][tx * 8 + 4];
#pragma unroll
            for (int r = 0; r < 8; r++)
#pragma unroll
                for (int c = 0; c < 8; c++) acc[r][c] += a[r] * bb[c];
        }
        __syncthreads();
    }
    const float scale = 0.125f;
#pragma unroll
    for (int r = 0; r < 8; r++) {
#pragma unroll
        for (int c = 0; c < 8; c += 4) {
            float4 v;
            v.x = acc[r][c + 0] * scale; v.y = acc[r][c + 1] * scale;
            v.z = acc[r][c + 2] * scale; v.w = acc[r][c + 3] * scale;
            *(float4*)(attn + ((size_t)bh * NN + q0 + ty * 8 + r) * NN + k0 + tx * 8 + c) = v;
        }
    }
}

// ---------------- per-row top-256 + double softmax (regs + shfl scans) ----------------
__global__ __launch_bounds__(256) void topk_softmax_kernel(float* __restrict__ attn) {
    int row = blockIdx.x;            // (b*16+h)*1024 + q
    int b = row >> 14;
    int tid = threadIdx.x;
    int lane = tid & 31, wid = tid >> 5;
    float* a = attn + (size_t)row * NN;
    __shared__ unsigned hist[256];
    __shared__ unsigned wtot[8];
    __shared__ float red8[8];
    __shared__ unsigned sel[3];
    __shared__ unsigned s_sk[1024];      // for rare tie path
    __shared__ unsigned char tieflag[1024];
    __shared__ int s_partial;

    float v[4];
    unsigned k[4];
    unsigned char mk[4];
    float lm = -3.4e38f;
#pragma unroll
    for (int i = 0; i < 4; i++) {
        int idx = tid + i * 256;
        v[i] = a[idx];
        k[i] = fkey(v[i]);
        s_sk[idx] = k[i];
        mk[i] = g_mask[b * NN + idx];
        lm = fmaxf(lm, v[i]);
    }
    if (tid == 0) { sel[0] = 0u; sel[1] = TOPK; }
    float m = bmax8(lm, red8, lane, wid);   // its syncs also publish sel[] init

    unsigned pmask = 0u;
#pragma unroll
    for (int shift = 24; shift >= 0; shift -= 8) {
        hist[tid] = 0u;
        unsigned prefix = sel[0];
        unsigned rem = sel[1];
        __syncthreads();
#pragma unroll
        for (int i = 0; i < 4; i++)
            if ((k[i] & pmask) == prefix) atomicAdd(&hist[(k[i] >> shift) & 255], 1u);
        __syncthreads();
        unsigned h = hist[tid];
        unsigned s = h;
#pragma unroll
        for (int off = 1; off < 32; off <<= 1) {
            unsigned n = __shfl_down_sync(0xffffffffu, s, off);
            if (lane + off < 32) s += n;
        }
        unsigned wt = __shfl_sync(0xffffffffu, s, 0);
        if (lane == 0) wtot[wid] = wt;
        __syncthreads();
        unsigned woff = 0;
        for (int w = wid + 1; w < 8; w++) woff += wtot[w];
        unsigned incl = s + woff;       // keys in bins >= tid
        unsigned above = incl - h;      // strictly greater bins
        if (above < rem && incl >= rem) {
            sel[0] = prefix | ((unsigned)tid << shift);
            sel[1] = rem - above;
            sel[2] = h;                 // at shift==0 this is exact cnt_eq
        }
        pmask |= (0xFFu << shift);
        __syncthreads();
    }
    unsigned tk = sel[0], rem = sel[1], cnt_eq = sel[2];

    if (tid == 0) {
        s_partial = (rem < cnt_eq);
        if (rem < cnt_eq) {             // rare: partial ties, lowest indices win
            unsigned taken = 0;
            for (int kk = 0; kk < 1024; kk++) {
                unsigned char f = (s_sk[kk] == tk && taken < rem) ? 1 : 0;
                tieflag[kk] = f;
                taken += f;
            }
        }
    }
    __syncthreads();
    int partial = s_partial;

    bool inc[4];
#pragma unroll
    for (int i = 0; i < 4; i++)
        inc[i] = (k[i] > tk) || (k[i] == tk && (!partial || tieflag[tid + i * 256]));

    float lS = 0.f;
#pragma unroll
    for (int i = 0; i < 4; i++)
        if (inc[i]) lS += __expf(v[i] - m);
    float S = bsum8(lS, red8, lane, wid);
    float invS = 1.f / S;

    float lz = 0.f, e[4];
#pragma unroll
    for (int i = 0; i < 4; i++) {
        e[i] = mk[i] ? 0.f : (inc[i] ? __expf(__expf(v[i] - m) * invS) : 1.f);
        lz += e[i];
    }
    float Z = bsum8(lz, red8, lane, wid);
    float invZ = 1.f / Z;
#pragma unroll
    for (int i = 0; i < 4; i++)
        a[tid + i * 256] = e[i] * invZ;
}

// ---------------- AV (R6 known-good): per (b,h): attn_w @ V -> x (B,N,C) ----------------
__global__ __launch_bounds__(256) void av_gemm_kernel(const float* __restrict__ attn,
                                                      const float* __restrict__ qkv,
                                                      float* __restrict__ x) {
    __shared__ float Ws[64][68];  // [kk][q]
    __shared__ float Vs[64][68];  // [kk][d]
    int tid = threadIdx.x;
    int q0 = blockIdx.x * 64;
    int bh = blockIdx.y;
    int b = bh >> 4, h = bh & 15;
    int r = tid >> 4;
    int c4 = (tid & 15) << 2;
    int qr = (tid >> 4) << 2;
    int dc = (tid & 15) << 2;
    float acc[4][4];
#pragma unroll
    for (int r2 = 0; r2 < 4; r2++)
#pragma unroll
        for (int c = 0; c < 4; c++) acc[r2][c] = 0.f;

    for (int kt = 0; kt < NN; kt += 64) {
#pragma unroll
        for (int i = 0; i < 4; i++) {
            int row = r + i * 16;
            float4 w = *(const float4*)(attn + ((size_t)bh * NN + q0 + row) * NN + kt + c4);
            Ws[c4 + 0][row] = w.x; Ws[c4 + 1][row] = w.y;
            Ws[c4 + 2][row] = w.z; Ws[c4 + 3][row] = w.w;
            float4 vv = *(const float4*)(qkv + ((size_t)b * NN + kt + row) * 3072 + 2048 + h * 64 + c4);
            *(float4*)&Vs[row][c4] = vv;
        }
        __syncthreads();
#pragma unroll
        for (int kk = 0; kk < 64; kk++) {
            float a[4], bb[4];
            *(float4*)a = *(float4*)&Ws[kk][qr];
            *(float4*)bb = *(float4*)&Vs[kk][dc];
#pragma unroll
            for (int r2 = 0; r2 < 4; r2++)
#pragma unroll
                for (int c = 0; c < 4; c++) acc[r2][c] += a[r2] * bb[c];
        }
        __syncthreads();
    }
#pragma unroll
    for (int r2 = 0; r2 < 4; r2++) {
        float4 v;
        v.x = acc[r2][0]; v.y = acc[r2][1]; v.z = acc[r2][2]; v.w = acc[r2][3];
        *(float4*)(x + ((size_t)b * NN + q0 + qr + r2) * NC + h * 64 + dc) = v;
    }
}

// ---------------- row layernorm over 1024 ----------------
__global__ __launch_bounds__(256) void ln_kernel(const float* __restrict__ in,
                                                 const float* __restrict__ g,
                                                 const float* __restrict__ bt,
                                                 float* __restrict__ out) {
    int row = blockIdx.x, tid = threadIdx.x;
    int lane = tid & 31, wid = tid >> 5;
    __shared__ float red8[8];
    const float* p = in + (size_t)row * 1024;
    float xv[4];
    float s = 0.f;
#pragma unroll
    for (int i = 0; i < 4; i++) {
        xv[i] = p[tid + i * 256];
        s += xv[i];
    }
    float mu = bsum8(s, red8, lane, wid) * (1.f / 1024.f);
    float vs = 0.f;
#pragma unroll
    for (int i = 0; i < 4; i++) {
        float d = xv[i] - mu;
        vs += d * d;
    }
    float var = bsum8(vs, red8, lane, wid) * (1.f / 1024.f);
    float rstd = rsqrtf(var + 1e-5f);
#pragma unroll
    for (int i = 0; i < 4; i++) {
        int idx = tid + i * 256;
        out[(size_t)row * 1024 + idx] = (xv[i] - mu) * rstd * g[idx] + bt[idx];
    }
}

// ---------------- vis token inverse norms ----------------
__global__ __launch_bounds__(256) void visnorm_kernel(const float* __restrict__ vis,
                                                      float* __restrict__ visinv) {
    int b = blockIdx.x, tid = threadIdx.x;
    int lane = tid & 31, wid = tid >> 5;
    __shared__ float red8[8];
    float s = 0.f;
#pragma unroll
    for (int i = 0; i < 4; i++) {
        float v = vis[b * 1024 + tid + i * 256];
        s += v * v;
    }
    float t = bsum8(s, red8, lane, wid);
    if (tid == 0) visinv[b] = 1.f / fmaxf(sqrtf(t), 1e-12f);
}

// ---------------- sim = sigmoid(beta + alpha * dot(vis_n, tf_n)), masked -> 0 ----------------
__global__ __launch_bounds__(256) void sim_kernel(const float* __restrict__ vis,
                                                  const float* __restrict__ tf,
                                                  const float* __restrict__ alpha,
                                                  const float* __restrict__ beta,
                                                  const float* __restrict__ visinv,
                                                  float* __restrict__ sim) {
    int bn = blockIdx.x;  // b*1024 + n
    int b = bn >> 10;
    int tid = threadIdx.x;
    int lane = tid & 31, wid = tid >> 5;
    __shared__ float red8[8];
    const float* vrow = vis + b * 1024;
    const float* trow = tf + (size_t)bn * 1024;
    float tv[4], vv[4];
    float q = 0.f;
#pragma unroll
    for (int i = 0; i < 4; i++) {
        int idx = tid + i * 256;
        tv[i] = trow[idx];
        vv[i] = vrow[idx];
        q += tv[i] * tv[i];
    }
    q = bsum8(q, red8, lane, wid);
    float invt = 1.f / fmaxf(sqrtf(q), 1e-12f);
    float vi = visinv[b];
    float d = 0.f;
#pragma unroll
    for (int i = 0; i < 4; i++)
        d += (vv[i] * vi) * (tv[i] * invt);
    d = bsum8(d, red8, lane, wid);
    if (tid == 0) {
        float s;
        if (g_mask[bn]) {
            s = 0.f;  // sigmoid(-inf)
        } else {
            float val = beta[0] + alpha[0] * d;
            s = 1.f / (1.f + __expf(-val));
        }
        sim[bn] = s;
    }
}

// ---------------- top-256 sim pooling + txt_token add ----------------
__global__ __launch_bounds__(256) void pool_kernel(const float* __restrict__ sim,
                                                   const float* __restrict__ tf,
                                                   const float* __restrict__ txt,
                                                   float* __restrict__ pooled) {
    int b = blockIdx.x, tid = threadIdx.x;
    __shared__ unsigned sk[1024];
    __shared__ unsigned hist[256];
    __shared__ unsigned ss[256];
    __shared__ unsigned sel[2];
    __shared__ unsigned char tieflag[1024];
    __shared__ int s_partial;
    __shared__ unsigned sc[256];
    __shared__ short list[256];
#pragma unroll
    for (int i = 0; i < 4; i++) {
        int idx = tid + i * 256;
        sk[idx] = fkey(sim[b * 1024 + idx]);
    }
    __syncthreads();
    radix_select_1024(sk, TOPK, hist, ss, sel, tid);
    unsigned tk = sel[0];
    unsigned rem = sel[1];
    if (tid == 0) hist[0] = 0;
    __syncthreads();
#pragma unroll
    for (int i = 0; i < 4; i++)
        if (sk[tid + i * 256] == tk) atomicAdd(&hist[0], 1u);
    __syncthreads();
    unsigned cnt_eq = hist[0];
    if (tid == 0) {
        s_partial = (rem < cnt_eq);
        if (rem < cnt_eq) {  // ties (masked entries are all exactly 0): lowest indices win
            unsigned taken = 0;
            for (int k = 0; k < 1024; k++) {
                unsigned char f = (sk[k] == tk && taken < rem) ? 1 : 0;
                tieflag[k] = f;
                taken += f;
            }
        }
    }
    __syncthreads();
    int partial = s_partial;

    int base = tid * 4;
    unsigned cnt = 0;
    unsigned char f[4];
#pragma unroll
    for (int j = 0; j < 4; j++) {
        int k = base + j;
        unsigned kk = sk[k];
        bool inc = (kk > tk) || (kk == tk && (!partial || tieflag[k]));
        f[j] = inc;
        cnt += inc;
    }
    sc[tid] = cnt;
    __syncthreads();
#pragma unroll
    for (int off = 1; off < 256; off <<= 1) {
        unsigned v = (tid >= off) ? sc[tid - off] : 0u;
        __syncthreads();
        sc[tid] += v;
        __syncthreads();
    }
    unsigned pos = sc[tid] - cnt;
#pragma unroll
    for (int j = 0; j < 4; j++)
        if (f[j]) list[pos++] = (short)(base + j);
    __syncthreads();

    float acc[4] = {0.f, 0.f, 0.f, 0.f};
    for (int j = 0; j < TOPK; j++) {
        int n = list[j];
        const float* rrow = tf + ((size_t)b * 1024 + n) * 1024;
#pragma unroll
        for (int i = 0; i < 4; i++) acc[i] += rrow[tid + i * 256];
    }
#pragma unroll
    for (int i = 0; i < 4; i++) {
        int c = tid + i * 256;
        pooled[b * 1024 + c] = acc[i] * (1.f / 256.f) + txt[b * 1024 + c];
    }
}

// ---------------- tt = LN(pooled @ Wp1 + bp1) ----------------
__global__ __launch_bounds__(256) void final_kernel(const float* __restrict__ pooled,
                                                    const float* __restrict__ W,
                                                    const float* __restrict__ bias,
                                                    const float* __restrict__ g,
                                                    const float* __restrict__ bt,
                                                    float* __restrict__ out) {
    int b = blockIdx.x, tid = threadIdx.x;
    int lane = tid & 31, wid = tid >> 5;
    __shared__ float ts[1024];
    __shared__ float red8[8];
#pragma unroll
    for (int i = 0; i < 4; i++) ts[tid + i * 256] = pooled[b * 1024 + tid + i * 256];
    __syncthreads();
    float acc[4] = {0.f, 0.f, 0.f, 0.f};
#pragma unroll 4
    for (int c = 0; c < 1024; c++) {
        float tc = ts[c];
        const float* wr = W + (size_t)c * 1024 + tid;
        acc[0] += tc * wr[0];
        acc[1] += tc * wr[256];
        acc[2] += tc * wr[512];
        acc[3] += tc * wr[768];
    }
    float ys[4];
    float s = 0.f;
#pragma unroll
    for (int i = 0; i < 4; i++) {
        ys[i] = acc[i] + bias[tid + i * 256];
        s += ys[i];
    }
    float mu = bsum8(s, red8, lane, wid) * (1.f / 1024.f);
    float vs = 0.f;
#pragma unroll
    for (int i = 0; i < 4; i++) {
        float d = ys[i] - mu;
        vs += d * d;
    }
    float var = bsum8(vs, red8, lane, wid) * (1.f / 1024.f);
    float rstd = rsqrtf(var + 1e-5f);
#pragma unroll
    for (int i = 0; i < 4; i++) {
        int idx = tid + i * 256;
        out[b * 1024 + idx] = (ys[i] - mu) * rstd * g[idx] + bt[idx];
    }
}

// ---------------- host launch ----------------
extern "C" void kernel_launch(void* const* d_in, const int* in_sizes, int n_in,
                              void* d_out, int out_size) {
    const float* txt_token = (const float*)d_in[0];
    const float* text_features = (const float*)d_in[1];
    const unsigned char* text_mask = (const unsigned char*)d_in[2];
    const float* vis_token = (const float*)d_in[3];
    int o = (n_in > 4 && in_sizes[4] == 1) ? 1 : 0;
    const float* Wqkv = (const float*)d_in[4 + o];
    const float* bqkv = (const float*)d_in[5 + o];
    const float* Wp2 = (const float*)d_in[6 + o];
    const float* bp2 = (const float*)d_in[7 + o];
    const float* ln2_g = (const float*)d_in[8 + o];
    const float* ln2_b = (const float*)d_in[9 + o];
    const float* sim_alpha = (const float*)d_in[10 + o];
    const float* sim_beta = (const float*)d_in[11 + o];
    const float* Wp1 = (const float*)d_in[12 + o];
    const float* bp1 = (const float*)d_in[13 + o];
    const float* ln1_g = (const float*)d_in[14 + o];
    const float* ln1_b = (const float*)d_in[15 + o];

    float* out = (float*)d_out;
    float* tt = out;                 // (8,1,1024)
    float* tf = out + NB * NC;       // (8,1024,1024)

    float *qkv, *attn, *x, *y, *simv, *pooled, *visinv;
    cudaGetSymbolAddress((void**)&qkv, g_qkv);
    cudaGetSymbolAddress((void**)&attn, g_attn);
    cudaGetSymbolAddress((void**)&x, g_x);
    cudaGetSymbolAddress((void**)&y, g_y);
    cudaGetSymbolAddress((void**)&simv, g_sim);
    cudaGetSymbolAddress((void**)&pooled, g_pooled);
    cudaGetSymbolAddress((void**)&visinv, g_visinv);

    // 0. canonicalize mask
    mask_canon_kernel<<<1, 256>>>(text_mask);
    // 1. qkv = X @ Wqkv + bqkv
    gemm_kernel<<<dim3(3072 / 128, 8192 / 128), 256>>>(text_features, Wqkv, bqkv, nullptr,
                                                       qkv, 8192, 3072, 1024);
    // 2. attn = Q K^T * scale   (128x128 tiles)
    attn_gemm_kernel<<<dim3(8, 8, 128), 256>>>(qkv, attn);
    // 3. top-256 + double softmax (in place)
    topk_softmax_kernel<<<NB * NH * NN, 256>>>(attn);
    // 4. x = attn_w @ V
    av_gemm_kernel<<<dim3(16, 128), 256>>>(attn, qkv, x);
    // 5. y = x @ Wp2 + bp2 + text_features
    gemm_kernel<<<dim3(1024 / 128, 8192 / 128), 256>>>(x, Wp2, bp2, text_features,
                                                       y, 8192, 1024, 1024);
    // 6. tf = layernorm(y)
    ln_kernel<<<8192, 256>>>(y, ln2_g, ln2_b, tf);
    // 7-8. sim
    visnorm_kernel<<<NB, 256>>>(vis_token, visinv);
    sim_kernel<<<NB * NN, 256>>>(vis_token, tf, sim_alpha, sim_beta, visinv, simv);
    // 9. pooled (+ txt_token)
    pool_kernel<<<NB, 256>>>(simv, tf, txt_token, pooled);
    // 10. tt = LN(pooled @ Wp1 + bp1)
    final_kernel<<<NB, 256>>>(pooled, Wp1, bp1, ln1_g, ln1_b, tt);
    (void)out_size;
}

// round 12
// speedup vs baseline: 1.6901x; 1.0490x over previous
#include <cuda_runtime.h>
#include <cstdint>

#define NB 8
#define NN 1024
#define NC 1024
#define NH 16
#define HD 64
#define TOPK 256

// ---------------- scratch (static device globals; no allocation) ----------------
__device__ float g_qkv[(size_t)NB * NN * 3 * NC];     // 8192 x 3072
__device__ float g_attn[(size_t)NB * NH * NN * NN];   // 128 x 1024 x 1024
__device__ float g_x[(size_t)NB * NN * NC];
__device__ float g_y[(size_t)NB * NN * NC];
__device__ float g_sim[NB * NN];
__device__ float g_pooled[NB * NC];
__device__ float g_visinv[NB];
__device__ unsigned char g_mask[NB * NN];             // canonical 0/1 mask

// ---------------- mask canonicalization (auto-detect uint8 vs int32 bool) ----------------
__global__ __launch_bounds__(256) void mask_canon_kernel(const unsigned char* __restrict__ raw) {
    __shared__ int red[256];
    int tid = threadIdx.x;
    int any = 0;
    for (int i = tid; i < NB * NN; i += 256)
        if ((i & 3) != 0 && raw[i] != 0) any = 1;
    red[tid] = any;
    __syncthreads();
#pragma unroll
    for (int off = 128; off > 0; off >>= 1) {
        if (tid < off) red[tid] |= red[tid + off];
        __syncthreads();
    }
    int is_u8 = red[0];
    const int* raw32 = (const int*)raw;
    for (int i = tid; i < NB * NN; i += 256) {
        unsigned char v = is_u8 ? (raw[i] != 0) : (raw32[i] != 0);
        g_mask[i] = v;
    }
}

// ---------------- helpers ----------------
__device__ __forceinline__ unsigned fkey(float f) {
    unsigned u = __float_as_uint(f);
    return (u & 0x80000000u) ? ~u : (u | 0x80000000u);
}

// shfl-based block reductions (256 threads, 8 warps). red8: 8-float smem scratch.
__device__ __forceinline__ float bsum8(float v, float* red8, int lane, int wid) {
#pragma unroll
    for (int off = 16; off > 0; off >>= 1) v += __shfl_xor_sync(0xffffffffu, v, off);
    __syncthreads();
    if (lane == 0) red8[wid] = v;
    __syncthreads();
    float t = red8[0];
#pragma unroll
    for (int w = 1; w < 8; w++) t += red8[w];
    return t;
}

__device__ __forceinline__ float bmax8(float v, float* red8, int lane, int wid) {
#pragma unroll
    for (int off = 16; off > 0; off >>= 1) v = fmaxf(v, __shfl_xor_sync(0xffffffffu, v, off));
    __syncthreads();
    if (lane == 0) red8[wid] = v;
    __syncthreads();
    float t = red8[0];
#pragma unroll
    for (int w = 1; w < 8; w++) t = fmaxf(t, red8[w]);
    return t;
}

// Exact descending radix select over 1024 smem keys (256 threads) — used by pool_kernel.
__device__ __forceinline__ void radix_select_1024(const unsigned* sk, unsigned kwant,
                                                  unsigned* hist, unsigned* ss,
                                                  unsigned* sel, int tid) {
    if (tid == 0) { sel[0] = 0u; sel[1] = kwant; }
    unsigned pmask = 0u;
    __syncthreads();
    for (int shift = 24; shift >= 0; shift -= 8) {
        hist[tid] = 0u;
        __syncthreads();
        unsigned prefix = sel[0];
#pragma unroll
        for (int i = 0; i < 4; i++) {
            unsigned k = sk[tid + i * 256];
            if ((k & pmask) == prefix) atomicAdd(&hist[(k >> shift) & 255], 1u);
        }
        __syncthreads();
        ss[tid] = hist[tid];
        __syncthreads();
#pragma unroll
        for (int off = 1; off < 256; off <<= 1) {
            unsigned v = (tid + off < 256) ? ss[tid + off] : 0u;
            __syncthreads();
            ss[tid] += v;
            __syncthreads();
        }
        unsigned rem = sel[1];
        unsigned h = hist[tid];
        unsigned above = (tid < 255) ? ss[tid + 1] : 0u;
        __syncthreads();
        if (above < rem && above + h >= rem) {
            sel[0] = prefix | ((unsigned)tid << shift);
            sel[1] = rem - above;
        }
        pmask |= (0xFFu << shift);
        __syncthreads();
    }
}

// ---------------- generic fp32 GEMM (known-good single-buffer): C = A*B + bias (+res) ----------------
__global__ __launch_bounds__(256) void gemm_kernel(const float* __restrict__ A,
                                                   const float* __restrict__ B,
                                                   const float* __restrict__ bias,
                                                   const float* __restrict__ res,
                                                   float* __restrict__ C,
                                                   int M, int N, int K) {
    __shared__ float As[16][132];  // [k][m]
    __shared__ float Bs[16][132];  // [k][n]
    int tid = threadIdx.x;
    int m0 = blockIdx.y * 128, n0 = blockIdx.x * 128;
    int ty = tid >> 4, tx = tid & 15;
    float acc[8][8];
#pragma unroll
    for (int r = 0; r < 8; r++)
#pragma unroll
        for (int c = 0; c < 8; c++) acc[r][c] = 0.f;

    for (int k0 = 0; k0 < K; k0 += 16) {
#pragma unroll
        for (int i = 0; i < 2; i++) {
            int lin = tid + i * 256;
            int m = lin >> 2;
            int kq = (lin & 3) << 2;
            float4 v = *(const float4*)(A + (size_t)(m0 + m) * K + k0 + kq);
            As[kq + 0][m] = v.x; As[kq + 1][m] = v.y;
            As[kq + 2][m] = v.z; As[kq + 3][m] = v.w;
        }
#pragma unroll
        for (int i = 0; i < 2; i++) {
            int lin = tid + i * 256;
            int k = lin >> 5;
            int nq = (lin & 31) << 2;
            *(float4*)(&Bs[k][nq]) = *(const float4*)(B + (size_t)(k0 + k) * N + n0 + nq);
        }
        __syncthreads();
#pragma unroll
        for (int k = 0; k < 16; k++) {
            float a[8], bb[8];
            *(float4*)&a[0] = *(float4*)&As[k][ty * 8];
            *(float4*)&a[4] = *(float4*)&As[k][ty * 8 + 4];
            *(float4*)&bb[0] = *(float4*)&Bs[k][tx * 8];
            *(float4*)&bb[4] = *(float4*)&Bs[k][tx * 8 + 4];
#pragma unroll
            for (int r = 0; r < 8; r++)
#pragma unroll
                for (int c = 0; c < 8; c++) acc[r][c] += a[r] * bb[c];
        }
        __syncthreads();
    }
#pragma unroll
    for (int r = 0; r < 8; r++) {
        int m = m0 + ty * 8 + r;
#pragma unroll
        for (int c = 0; c < 8; c += 4) {
            int n = n0 + tx * 8 + c;
            float4 v;
            v.x = acc[r][c + 0] + bias[n + 0];
            v.y = acc[r][c + 1] + bias[n + 1];
            v.z = acc[r][c + 2] + bias[n + 2];
            v.w = acc[r][c + 3] + bias[n + 3];
            if (res) {
                float4 rr = *(const float4*)(res + (size_t)m * N + n);
                v.x += rr.x; v.y += rr.y; v.z += rr.z; v.w += rr.w;
            }
            *(float4*)(C + (size_t)m * N + n) = v;
        }
    }
}

// ---------------- attn scores: 128x128 tile per block, BK=32 (K=64: 2 iters) ----------------
__global__ __launch_bounds__(256) void attn_gemm_kernel(const float* __restrict__ qkv,
                                                        float* __restrict__ attn) {
    __shared__ float Qs[32][132];  // [d][q]
    __shared__ float Ks[32][132];  // [d][ktok]
    int tid = threadIdx.x;
    int q0 = blockIdx.x * 128, k0 = blockIdx.y * 128;
    int bh = blockIdx.z;
    int b = bh >> 4, h = bh & 15;
    size_t qbase = ((size_t)b * NN + q0) * 3072 + h * 64;
    size_t kbase = ((size_t)b * NN + k0) * 3072 + 1024 + h * 64;
    int ty = tid >> 4, tx = tid & 15;
    float acc[8][8];
#pragma unroll
    for (int r = 0; r < 8; r++)
#pragma unroll
        for (int c = 0; c < 8; c++) acc[r][c] = 0.f;

    for (int d0 = 0; d0 < 64; d0 += 32) {
#pragma unroll
        for (int i = 0; i < 4; i++) {
            int lin = tid + i * 256;
            int m = lin >> 3;
            int dq = (lin & 7) << 2;
            float4 qv = *(const float4*)(qkv + qbase + (size_t)m * 3072 + d0 + dq);
            Qs[dq + 0][m] = qv.x; Qs[dq + 1][m] = qv.y;
            Qs[dq + 2][m] = qv.z; Qs[dq + 3][m] = qv.w;
            float4 kv = *(const float4*)(qkv + kbase + (size_t)m * 3072 + d0 + dq);
            Ks[dq + 0][m] = kv.x; Ks[dq + 1][m] = kv.y;
            Ks[dq + 2][m] = kv.z; Ks[dq + 3][m] = kv.w;
        }
        __syncthreads();
#pragma unroll
        for (int d = 0; d < 32; d++) {
            float a[8], bb[8];
            *(float4*)&a[0] = *(float4*)&Qs[d][ty * 8];
            *(float4*)&a[4] = *(float4*)&Qs[d][ty * 8 + 4];
            *(float4*)&bb[0] = *(float4*)&Ks[d][tx * 8];
            *(float4*)&bb[4] = *(float4*)&Ks[d][tx * 8 + 4];
#pragma unroll
            for (int r = 0; r < 8; r++)
#pragma unroll
                for (int c = 0; c < 8; c++) acc[r][c] += a[r] * bb[c];
        }
        __syncthreads();
    }
    const float scale = 0.125f;
#pragma unroll
    for (int r = 0; r < 8; r++) {
#pragma unroll
        for (int c = 0; c < 8; c += 4) {
            float4 v;
            v.x = acc[r][c + 0] * scale; v.y = acc[r][c + 1] * scale;
            v.z = acc[r][c + 2] * scale; v.w = acc[r][c + 3] * scale;
            *(float4*)(attn + ((size_t)bh * NN + q0 + ty * 8 + r) * NN + k0 + tx * 8 + c) = v;
        }
    }
}

// ---------------- per-row top-256 + double softmax (regs + shfl scans) ----------------
__global__ __launch_bounds__(256) void topk_softmax_kernel(float* __restrict__ attn) {
    int row = blockIdx.x;            // (b*16+h)*1024 + q
    int b = row >> 14;
    int tid = threadIdx.x;
    int lane = tid & 31, wid = tid >> 5;
    float* a = attn + (size_t)row * NN;
    __shared__ unsigned hist[256];
    __shared__ unsigned wtot[8];
    __shared__ float red8[8];
    __shared__ unsigned sel[3];
    __shared__ unsigned char tieflag[1024];  // only touched on the rare partial-tie path
    __shared__ int s_partial;

    float v[4];
    unsigned k[4];
    unsigned char mk[4];
    float lm = -3.4e38f;
#pragma unroll
    for (int i = 0; i < 4; i++) {
        int idx = tid + i * 256;
        v[i] = a[idx];
        k[i] = fkey(v[i]);
        mk[i] = g_mask[b * NN + idx];
        lm = fmaxf(lm, v[i]);
    }
    if (tid == 0) { sel[0] = 0u; sel[1] = TOPK; }
    float m = bmax8(lm, red8, lane, wid);   // its syncs also publish sel[] init

    unsigned pmask = 0u;
#pragma unroll
    for (int shift = 24; shift >= 0; shift -= 8) {
        hist[tid] = 0u;
        unsigned prefix = sel[0];
        unsigned rem = sel[1];
        __syncthreads();
#pragma unroll
        for (int i = 0; i < 4; i++)
            if ((k[i] & pmask) == prefix) atomicAdd(&hist[(k[i] >> shift) & 255], 1u);
        __syncthreads();
        unsigned h = hist[tid];
        unsigned s = h;
#pragma unroll
        for (int off = 1; off < 32; off <<= 1) {
            unsigned n = __shfl_down_sync(0xffffffffu, s, off);
            if (lane + off < 32) s += n;
        }
        unsigned wt = __shfl_sync(0xffffffffu, s, 0);
        if (lane == 0) wtot[wid] = wt;
        __syncthreads();
        unsigned woff = 0;
        for (int w = wid + 1; w < 8; w++) woff += wtot[w];
        unsigned incl = s + woff;       // keys in bins >= tid
        unsigned above = incl - h;      // strictly greater bins
        if (above < rem && incl >= rem) {
            sel[0] = prefix | ((unsigned)tid << shift);
            sel[1] = rem - above;
            sel[2] = h;                 // at shift==0 this is exact cnt_eq
        }
        pmask |= (0xFFu << shift);
        __syncthreads();
    }
    unsigned tk = sel[0], rem = sel[1], cnt_eq = sel[2];

    if (tid == 0) s_partial = (rem < cnt_eq);
    __syncthreads();
    int partial = s_partial;
    if (partial) {                      // rare: partial ties, lowest indices win
        if (tid == 0) {
            unsigned taken = 0;
            for (int kk = 0; kk < 1024; kk++) {
                unsigned char f = (fkey(a[kk]) == tk && taken < rem) ? 1 : 0;
                tieflag[kk] = f;
                taken += f;
            }
        }
        __syncthreads();
    }

    bool inc[4];
#pragma unroll
    for (int i = 0; i < 4; i++)
        inc[i] = (k[i] > tk) || (k[i] == tk && (!partial || tieflag[tid + i * 256]));

    float lS = 0.f;
#pragma unroll
    for (int i = 0; i < 4; i++)
        if (inc[i]) lS += __expf(v[i] - m);
    float S = bsum8(lS, red8, lane, wid);
    float invS = 1.f / S;

    float lz = 0.f, e[4];
#pragma unroll
    for (int i = 0; i < 4; i++) {
        e[i] = mk[i] ? 0.f : (inc[i] ? __expf(__expf(v[i] - m) * invS) : 1.f);
        lz += e[i];
    }
    float Z = bsum8(lz, red8, lane, wid);
    float invZ = 1.f / Z;
#pragma unroll
    for (int i = 0; i < 4; i++)
        a[tid + i * 256] = e[i] * invZ;
}

// ---------------- AV: two heads per block -> 128(q) x 128(2*hd) tile, single-buffer ----------------
__global__ __launch_bounds__(256) void av_gemm_kernel(const float* __restrict__ attn,
                                                      const float* __restrict__ qkv,
                                                      float* __restrict__ x) {
    __shared__ float Ws0[16][132];  // [k][q] head 2hp
    __shared__ float Ws1[16][132];  // [k][q] head 2hp+1
    __shared__ float Vs[16][132];   // [k][d 0..127 = both heads' 64+64 cols]
    int tid = threadIdx.x;
    int q0 = blockIdx.x * 128;
    int bhp = blockIdx.y;            // b*8 + hp
    int b = bhp >> 3, hp = bhp & 7;
    int bh0 = b * 16 + hp * 2;
    int ty = tid >> 4, tx = tid & 15;
    // loader indices: Ws*: 512 float4 each -> 2/thread; Vs: 512 float4 -> 2/thread
    int wq0 = tid >> 1;              // two threads per q-row, each 1 float4... no:
    // Ws: row = lin>>2 (0..127), kq = (lin&3)*4, lin in [0,512)
    const float* w0base = attn + (size_t)bh0 * NN * NN;
    const float* w1base = attn + (size_t)(bh0 + 1) * NN * NN;
    const float* vbase = qkv + (size_t)b * NN * 3072 + 2048 + hp * 128;
    (void)wq0;

    float acc[8][8];
#pragma unroll
    for (int r = 0; r < 8; r++)
#pragma unroll
        for (int c = 0; c < 8; c++) acc[r][c] = 0.f;

    float (*Wsel)[132] = (tx < 8) ? Ws0 : Ws1;
    int txm = (tx & 7) * 8 + ((tx < 8) ? 0 : 64);  // unused for Vs (Vs indexed by tx*8 directly)
    (void)txm;

    for (int kt = 0; kt < NN; kt += 16) {
#pragma unroll
        for (int i = 0; i < 2; i++) {
            int lin = tid + i * 256;
            int row = lin >> 2;              // q-row 0..127
            int kq = (lin & 3) << 2;         // k 0,4,8,12
            float4 w0 = *(const float4*)(w0base + (size_t)(q0 + row) * NN + kt + kq);
            Ws0[kq + 0][row] = w0.x; Ws0[kq + 1][row] = w0.y;
            Ws0[kq + 2][row] = w0.z; Ws0[kq + 3][row] = w0.w;
            float4 w1 = *(const float4*)(w1base + (size_t)(q0 + row) * NN + kt + kq);
            Ws1[kq + 0][row] = w1.x; Ws1[kq + 1][row] = w1.y;
            Ws1[kq + 2][row] = w1.z; Ws1[kq + 3][row] = w1.w;
            int vk = lin >> 5;               // k 0..15
            int vd = (lin & 31) << 2;        // d 0..124
            *(float4*)(&Vs[vk][vd]) = *(const float4*)(vbase + (size_t)(kt + vk) * 3072 + vd);
        }
        __syncthreads();
#pragma unroll
        for (int kk = 0; kk < 16; kk++) {
            float a[8], bb[8];
            *(float4*)&a[0] = *(float4*)&Wsel[kk][ty * 8];
            *(float4*)&a[4] = *(float4*)&Wsel[kk][ty * 8 + 4];
            *(float4*)&bb[0] = *(float4*)&Vs[kk][tx * 8];
            *(float4*)&bb[4] = *(float4*)&Vs[kk][tx * 8 + 4];
#pragma unroll
            for (int r = 0; r < 8; r++)
#pragma unroll
                for (int c = 0; c < 8; c++) acc[r][c] += a[r] * bb[c];
        }
        __syncthreads();
    }
#pragma unroll
    for (int r = 0; r < 8; r++) {
#pragma unroll
        for (int c = 0; c < 8; c += 4) {
            float4 v;
            v.x = acc[r][c + 0]; v.y = acc[r][c + 1];
            v.z = acc[r][c + 2]; v.w = acc[r][c + 3];
            *(float4*)(x + ((size_t)b * NN + q0 + ty * 8 + r) * NC + hp * 128 + tx * 8 + c) = v;
        }
    }
}

// ---------------- row layernorm over 1024 ----------------
__global__ __launch_bounds__(256) void ln_kernel(const float* __restrict__ in,
                                                 const float* __restrict__ g,
                                                 const float* __restrict__ bt,
                                                 float* __restrict__ out) {
    int row = blockIdx.x, tid = threadIdx.x;
    int lane = tid & 31, wid = tid >> 5;
    __shared__ float red8[8];
    const float* p = in + (size_t)row * 1024;
    float xv[4];
    float s = 0.f;
#pragma unroll
    for (int i = 0; i < 4; i++) {
        xv[i] = p[tid + i * 256];
        s += xv[i];
    }
    float mu = bsum8(s, red8, lane, wid) * (1.f / 1024.f);
    float vs = 0.f;
#pragma unroll
    for (int i = 0; i < 4; i++) {
        float d = xv[i] - mu;
        vs += d * d;
    }
    float var = bsum8(vs, red8, lane, wid) * (1.f / 1024.f);
    float rstd = rsqrtf(var + 1e-5f);
#pragma unroll
    for (int i = 0; i < 4; i++) {
        int idx = tid + i * 256;
        out[(size_t)row * 1024 + idx] = (xv[i] - mu) * rstd * g[idx] + bt[idx];
    }
}

// ---------------- vis token inverse norms ----------------
__global__ __launch_bounds__(256) void visnorm_kernel(const float* __restrict__ vis,
                                                      float* __restrict__ visinv) {
    int b = blockIdx.x, tid = threadIdx.x;
    int lane = tid & 31, wid = tid >> 5;
    __shared__ float red8[8];
    float s = 0.f;
#pragma unroll
    for (int i = 0; i < 4; i++) {
        float v = vis[b * 1024 + tid + i * 256];
        s += v * v;
    }
    float t = bsum8(s, red8, lane, wid);
    if (tid == 0) visinv[b] = 1.f / fmaxf(sqrtf(t), 1e-12f);
}

// ---------------- sim = sigmoid(beta + alpha * dot(vis_n, tf_n)), masked -> 0 ----------------
__global__ __launch_bounds__(256) void sim_kernel(const float* __restrict__ vis,
                                                  const float* __restrict__ tf,
                                                  const float* __restrict__ alpha,
                                                  const float* __restrict__ beta,
                                                  const float* __restrict__ visinv,
                                                  float* __restrict__ sim) {
    int bn = blockIdx.x;  // b*1024 + n
    int b = bn >> 10;
    int tid = threadIdx.x;
    int lane = tid & 31, wid = tid >> 5;
    __shared__ float red8[8];
    const float* vrow = vis + b * 1024;
    const float* trow = tf + (size_t)bn * 1024;
    float tv[4], vv[4];
    float q = 0.f;
#pragma unroll
    for (int i = 0; i < 4; i++) {
        int idx = tid + i * 256;
        tv[i] = trow[idx];
        vv[i] = vrow[idx];
        q += tv[i] * tv[i];
    }
    q = bsum8(q, red8, lane, wid);
    float invt = 1.f / fmaxf(sqrtf(q), 1e-12f);
    float vi = visinv[b];
    float d = 0.f;
#pragma unroll
    for (int i = 0; i < 4; i++)
        d += (vv[i] * vi) * (tv[i] * invt);
    d = bsum8(d, red8, lane, wid);
    if (tid == 0) {
        float s;
        if (g_mask[bn]) {
            s = 0.f;  // sigmoid(-inf)
        } else {
            float val = beta[0] + alpha[0] * d;
            s = 1.f / (1.f + __expf(-val));
        }
        sim[bn] = s;
    }
}

// ---------------- top-256 sim pooling + txt_token add ----------------
__global__ __launch_bounds__(256) void pool_kernel(const float* __restrict__ sim,
                                                   const float* __restrict__ tf,
                                                   const float* __restrict__ txt,
                                                   float* __restrict__ pooled) {
    int b = blockIdx.x, tid = threadIdx.x;
    __shared__ unsigned sk[1024];
    __shared__ unsigned hist[256];
    __shared__ unsigned ss[256];
    __shared__ unsigned sel[2];
    __shared__ unsigned char tieflag[1024];
    __shared__ int s_partial;
    __shared__ unsigned sc[256];
    __shared__ short list[256];
#pragma unroll
    for (int i = 0; i < 4; i++) {
        int idx = tid + i * 256;
        sk[idx] = fkey(sim[b * 1024 + idx]);
    }
    __syncthreads();
    radix_select_1024(sk, TOPK, hist, ss, sel, tid);
    unsigned tk = sel[0];
    unsigned rem = sel[1];
    if (tid == 0) hist[0] = 0;
    __syncthreads();
#pragma unroll
    for (int i = 0; i < 4; i++)
        if (sk[tid + i * 256] == tk) atomicAdd(&hist[0], 1u);
    __syncthreads();
    unsigned cnt_eq = hist[0];
    if (tid == 0) {
        s_partial = (rem < cnt_eq);
        if (rem < cnt_eq) {  // ties (masked entries are all exactly 0): lowest indices win
            unsigned taken = 0;
            for (int k = 0; k < 1024; k++) {
                unsigned char f = (sk[k] == tk && taken < rem) ? 1 : 0;
                tieflag[k] = f;
                taken += f;
            }
        }
    }
    __syncthreads();
    int partial = s_partial;

    int base = tid * 4;
    unsigned cnt = 0;
    unsigned char f[4];
#pragma unroll
    for (int j = 0; j < 4; j++) {
        int k = base + j;
        unsigned kk = sk[k];
        bool inc = (kk > tk) || (kk == tk && (!partial || tieflag[k]));
        f[j] = inc;
        cnt += inc;
    }
    sc[tid] = cnt;
    __syncthreads();
#pragma unroll
    for (int off = 1; off < 256; off <<= 1) {
        unsigned v = (tid >= off) ? sc[tid - off] : 0u;
        __syncthreads();
        sc[tid] += v;
        __syncthreads();
    }
    unsigned pos = sc[tid] - cnt;
#pragma unroll
    for (int j = 0; j < 4; j++)
        if (f[j]) list[pos++] = (short)(base + j);
    __syncthreads();

    float acc[4] = {0.f, 0.f, 0.f, 0.f};
    for (int j = 0; j < TOPK; j++) {
        int n = list[j];
        const float* rrow = tf + ((size_t)b * 1024 + n) * 1024;
#pragma unroll
        for (int i = 0; i < 4; i++) acc[i] += rrow[tid + i * 256];
    }
#pragma unroll
    for (int i = 0; i < 4; i++) {
        int c = tid + i * 256;
        pooled[b * 1024 + c] = acc[i] * (1.f / 256.f) + txt[b * 1024 + c];
    }
}

// ---------------- tt = LN(pooled @ Wp1 + bp1) ----------------
__global__ __launch_bounds__(256) void final_kernel(const float* __restrict__ pooled,
                                                    const float* __restrict__ W,
                                                    const float* __restrict__ bias,
                                                    const float* __restrict__ g,
                                                    const float* __restrict__ bt,
                                                    float* __restrict__ out) {
    int b = blockIdx.x, tid = threadIdx.x;
    int lane = tid & 31, wid = tid >> 5;
    __shared__ float ts[1024];
    __shared__ float red8[8];
#pragma unroll
    for (int i = 0; i < 4; i++) ts[tid + i * 256] = pooled[b * 1024 + tid + i * 256];
    __syncthreads();
    float acc[4] = {0.f, 0.f, 0.f, 0.f};
#pragma unroll 4
    for (int c = 0; c < 1024; c++) {
        float tc = ts[c];
        const float* wr = W + (size_t)c * 1024 + tid;
        acc[0] += tc * wr[0];
        acc[1] += tc * wr[256];
        acc[2] += tc * wr[512];
        acc[3] += tc * wr[768];
    }
    float ys[4];
    float s = 0.f;
#pragma unroll
    for (int i = 0; i < 4; i++) {
        ys[i] = acc[i] + bias[tid + i * 256];
        s += ys[i];
    }
    float mu = bsum8(s, red8, lane, wid) * (1.f / 1024.f);
    float vs = 0.f;
#pragma unroll
    for (int i = 0; i < 4; i++) {
        float d = ys[i] - mu;
        vs += d * d;
    }
    float var = bsum8(vs, red8, lane, wid) * (1.f / 1024.f);
    float rstd = rsqrtf(var + 1e-5f);
#pragma unroll
    for (int i = 0; i < 4; i++) {
        int idx = tid + i * 256;
        out[b * 1024 + idx] = (ys[i] - mu) * rstd * g[idx] + bt[idx];
    }
}

// ---------------- host launch ----------------
extern "C" void kernel_launch(void* const* d_in, const int* in_sizes, int n_in,
                              void* d_out, int out_size) {
    const float* txt_token = (const float*)d_in[0];
    const float* text_features = (const float*)d_in[1];
    const unsigned char* text_mask = (const unsigned char*)d_in[2];
    const float* vis_token = (const float*)d_in[3];
    int o = (n_in > 4 && in_sizes[4] == 1) ? 1 : 0;
    const float* Wqkv = (const float*)d_in[4 + o];
    const float* bqkv = (const float*)d_in[5 + o];
    const float* Wp2 = (const float*)d_in[6 + o];
    const float* bp2 = (const float*)d_in[7 + o];
    const float* ln2_g = (const float*)d_in[8 + o];
    const float* ln2_b = (const float*)d_in[9 + o];
    const float* sim_alpha = (const float*)d_in[10 + o];
    const float* sim_beta = (const float*)d_in[11 + o];
    const float* Wp1 = (const float*)d_in[12 + o];
    const float* bp1 = (const float*)d_in[13 + o];
    const float* ln1_g = (const float*)d_in[14 + o];
    const float* ln1_b = (const float*)d_in[15 + o];

    float* out = (float*)d_out;
    float* tt = out;                 // (8,1,1024)
    float* tf = out + NB * NC;       // (8,1024,1024)

    float *qkv, *attn, *x, *y, *simv, *pooled, *visinv;
    cudaGetSymbolAddress((void**)&qkv, g_qkv);
    cudaGetSymbolAddress((void**)&attn, g_attn);
    cudaGetSymbolAddress((void**)&x, g_x);
    cudaGetSymbolAddress((void**)&y, g_y);
    cudaGetSymbolAddress((void**)&simv, g_sim);
    cudaGetSymbolAddress((void**)&pooled, g_pooled);
    cudaGetSymbolAddress((void**)&visinv, g_visinv);

    // 0. canonicalize mask
    mask_canon_kernel<<<1, 256>>>(text_mask);
    // 1. qkv = X @ Wqkv + bqkv
    gemm_kernel<<<dim3(3072 / 128, 8192 / 128), 256>>>(text_features, Wqkv, bqkv, nullptr,
                                                       qkv, 8192, 3072, 1024);
    // 2. attn = Q K^T * scale   (128x128 tiles)
    attn_gemm_kernel<<<dim3(8, 8, 128), 256>>>(qkv, attn);
    // 3. top-256 + double softmax (in place)
    topk_softmax_kernel<<<NB * NH * NN, 256>>>(attn);
    // 4. x = attn_w @ V  (two heads per block, 128x128 tile)
    av_gemm_kernel<<<dim3(8, 64), 256>>>(attn, qkv, x);
    // 5. y = x @ Wp2 + bp2 + text_features
    gemm_kernel<<<dim3(1024 / 128, 8192 / 128), 256>>>(x, Wp2, bp2, text_features,
                                                       y, 8192, 1024, 1024);
    // 6. tf = layernorm(y)
    ln_kernel<<<8192, 256>>>(y, ln2_g, ln2_b, tf);
    // 7-8. sim
    visnorm_kernel<<<NB, 256>>>(vis_token, visinv);
    sim_kernel<<<NB * NN, 256>>>(vis_token, tf, sim_alpha, sim_beta, visinv, simv);
    // 9. pooled (+ txt_token)
    pool_kernel<<<NB, 256>>>(simv, tf, txt_token, pooled);
    // 10. tt = LN(pooled @ Wp1 + bp1)
    final_kernel<<<NB, 256>>>(pooled, Wp1, bp1, ln1_g, ln1_b, tt);
    (void)out_size;
}